// round 1
// baseline (speedup 1.0000x reference)
#include <cuda_runtime.h>

// Problem constants (fixed by the reference)
#define NN 100000
#define EE 3200000
#define DD 128
#define NB_SCAN 98   // ceil(NN / 1024)

// ---------------- static device scratch (no allocation allowed) --------------
__device__ int   g_cnt[NN];                 // histogram counts, then scatter cursor
__device__ int   g_rptr[NN + 1];            // CSR row pointers
__device__ int   g_bsum[128];               // block sums for 2-level scan
__device__ int   g_cols[EE];                // CSR col indices (row-sorted)
__device__ float g_vals[EE];                // CSR values (row-sorted)
__device__ float g_Z[3][(size_t)NN * DD];   // Z1, Z2, Z3 (Z0 == X input)

// ---------------- CSR build ----------------

__global__ void k_zero_cnt() {
    int i = blockIdx.x * blockDim.x + threadIdx.x;
    if (i < NN) g_cnt[i] = 0;
}

__global__ void k_hist(const int* __restrict__ row) {
    int e = blockIdx.x * blockDim.x + threadIdx.x;
    if (e < EE) atomicAdd(&g_cnt[row[e]], 1);
}

// Per-block exclusive scan of counts (1024/block), emits block totals.
__global__ void k_scan1() {
    __shared__ int s[1024];
    int t = threadIdx.x;
    int i = blockIdx.x * 1024 + t;
    int v = (i < NN) ? g_cnt[i] : 0;
    s[t] = v;
    __syncthreads();
    for (int off = 1; off < 1024; off <<= 1) {
        int u = (t >= off) ? s[t - off] : 0;
        __syncthreads();
        s[t] += u;
        __syncthreads();
    }
    if (i < NN) g_rptr[i] = s[t] - v;          // exclusive within block
    if (t == 1023) g_bsum[blockIdx.x] = s[1023];
}

// Scan the 98 block sums (single block).
__global__ void k_scan2() {
    __shared__ int s[128];
    int t = threadIdx.x;
    int v = (t < NB_SCAN) ? g_bsum[t] : 0;
    s[t] = v;
    __syncthreads();
    for (int off = 1; off < 128; off <<= 1) {
        int u = (t >= off) ? s[t - off] : 0;
        __syncthreads();
        s[t] += u;
        __syncthreads();
    }
    g_bsum[t] = s[t] - v;                       // exclusive
}

// Add block offsets; seed scatter cursors; close row_ptr.
__global__ void k_scan3() {
    int i = blockIdx.x * blockDim.x + threadIdx.x;
    if (i < NN) {
        int p = g_rptr[i] + g_bsum[i >> 10];
        g_rptr[i] = p;
        g_cnt[i]  = p;
    }
    if (i == 0) g_rptr[NN] = EE;
}

__global__ void k_scatter(const int* __restrict__ row, const int* __restrict__ col,
                          const float* __restrict__ val) {
    int e = blockIdx.x * blockDim.x + threadIdx.x;
    if (e < EE) {
        int r = row[e];
        int p = atomicAdd(&g_cnt[r], 1);
        g_cols[p] = col[e];
        g_vals[p] = val[e];
    }
}

// ---------------- SpMM: warp per row, atomic-free ----------------
// Zout[r, :] = sum_{e in row r} val[e] * Zin[col[e], :]
__global__ void __launch_bounds__(256) k_spmm(const float* __restrict__ Xin, int hop) {
    const float4* __restrict__ Zin =
        (hop == 0) ? (const float4*)Xin : (const float4*)&g_Z[hop - 1][0];
    float4* __restrict__ Zout = (float4*)&g_Z[hop][0];

    int w = (blockIdx.x * blockDim.x + threadIdx.x) >> 5;
    if (w >= NN) return;
    int lane = threadIdx.x & 31;

    int s = g_rptr[w];
    int e = g_rptr[w + 1];

    float4 acc = make_float4(0.f, 0.f, 0.f, 0.f);
    int i = s;
    // 4-way unroll for MLP on the Z gathers
    for (; i + 4 <= e; i += 4) {
        int   c0 = g_cols[i],     c1 = g_cols[i + 1],
              c2 = g_cols[i + 2], c3 = g_cols[i + 3];
        float v0 = g_vals[i],     v1 = g_vals[i + 1],
              v2 = g_vals[i + 2], v3 = g_vals[i + 3];
        float4 z0 = Zin[c0 * 32 + lane];
        float4 z1 = Zin[c1 * 32 + lane];
        float4 z2 = Zin[c2 * 32 + lane];
        float4 z3 = Zin[c3 * 32 + lane];
        acc.x += v0 * z0.x; acc.y += v0 * z0.y; acc.z += v0 * z0.z; acc.w += v0 * z0.w;
        acc.x += v1 * z1.x; acc.y += v1 * z1.y; acc.z += v1 * z1.z; acc.w += v1 * z1.w;
        acc.x += v2 * z2.x; acc.y += v2 * z2.y; acc.z += v2 * z2.z; acc.w += v2 * z2.w;
        acc.x += v3 * z3.x; acc.y += v3 * z3.y; acc.z += v3 * z3.z; acc.w += v3 * z3.w;
    }
    for (; i < e; i++) {
        int c = g_cols[i];
        float v = g_vals[i];
        float4 z = Zin[c * 32 + lane];
        acc.x += v * z.x; acc.y += v * z.y; acc.z += v * z.z; acc.w += v * z.w;
    }
    Zout[w * 32 + lane] = acc;
}

// ---------------- Fused concat + Linear ----------------
// out[i, j] = sum_{seg=0..3} sum_{k=0..127} Zseg[i,k] * W[seg*128+k, j] + b[j]
// Block: 64 rows x 128 cols. Thread (tx: 4 cols, ty: 8 rows) -> 8x4 register tile.
__global__ void __launch_bounds__(256) k_gemm(const float* __restrict__ X,
                                              const float* __restrict__ W,
                                              const float* __restrict__ bias,
                                              float* __restrict__ out) {
    __shared__ float sH[64][36];     // [row][k-chunk] padded for conflict-free f4 stores
    __shared__ float sW[32][128];    // [k][j]

    int tid = threadIdx.x;
    int tx = tid & 31;               // column group: j0 = tx*4
    int ty = tid >> 5;               // row group:    r0 = ty*8
    int rowBase = blockIdx.x * 64;

    float acc[8][4];
#pragma unroll
    for (int r = 0; r < 8; r++)
#pragma unroll
        for (int c = 0; c < 4; c++) acc[r][c] = 0.f;

    for (int seg = 0; seg < 4; seg++) {
        const float* __restrict__ Zsrc = (seg == 0) ? X : &g_Z[seg - 1][0];
        for (int kk = 0; kk < 128; kk += 32) {
            // Stage H tile: 64 rows x 32 k = 512 float4; 2 per thread
#pragma unroll
            for (int u = 0; u < 2; u++) {
                int f  = tid + u * 256;
                int r  = f >> 3;
                int ko = (f & 7) * 4;
                int grow = rowBase + r;
                float4 hv = make_float4(0.f, 0.f, 0.f, 0.f);
                if (grow < NN)
                    hv = *(const float4*)&Zsrc[(size_t)grow * DD + kk + ko];
                *(float4*)&sH[r][ko] = hv;
            }
            // Stage W tile: 32 k x 128 j = 1024 float4; 4 per thread
#pragma unroll
            for (int u = 0; u < 4; u++) {
                int f = tid + u * 256;
                int k = f >> 5;
                int j = (f & 31) * 4;
                *(float4*)&sW[k][j] =
                    *(const float4*)&W[(size_t)(seg * 128 + kk + k) * DD + j];
            }
            __syncthreads();
#pragma unroll
            for (int k = 0; k < 32; k++) {
                float4 wv = *(float4*)&sW[k][tx * 4];
#pragma unroll
                for (int rr = 0; rr < 8; rr++) {
                    float h = sH[ty * 8 + rr][k];
                    acc[rr][0] += h * wv.x;
                    acc[rr][1] += h * wv.y;
                    acc[rr][2] += h * wv.z;
                    acc[rr][3] += h * wv.w;
                }
            }
            __syncthreads();
        }
    }

    float4 bb = *(const float4*)&bias[tx * 4];
#pragma unroll
    for (int rr = 0; rr < 8; rr++) {
        int grow = rowBase + ty * 8 + rr;
        if (grow < NN) {
            float4 o;
            o.x = acc[rr][0] + bb.x;
            o.y = acc[rr][1] + bb.y;
            o.z = acc[rr][2] + bb.z;
            o.w = acc[rr][3] + bb.w;
            *(float4*)&out[(size_t)grow * DD + tx * 4] = o;
        }
    }
}

// ---------------- launch ----------------
extern "C" void kernel_launch(void* const* d_in, const int* in_sizes, int n_in,
                              void* d_out, int out_size) {
    const float* X  = (const float*)d_in[0];
    const int*   Ar = (const int*)d_in[1];
    const int*   Ac = (const int*)d_in[2];
    const float* Av = (const float*)d_in[3];
    const float* W  = (const float*)d_in[4];
    const float* b  = (const float*)d_in[5];
    float* out = (float*)d_out;

    // CSR build (once per launch, reused by all 3 hops)
    k_zero_cnt<<<(NN + 255) / 256, 256>>>();
    k_hist<<<(EE + 255) / 256, 256>>>(Ar);
    k_scan1<<<NB_SCAN, 1024>>>();
    k_scan2<<<1, 128>>>();
    k_scan3<<<(NN + 255) / 256, 256>>>();
    k_scatter<<<(EE + 255) / 256, 256>>>(Ar, Ac, Av);

    // 3 SpMM hops: warp per row
    int spmm_blocks = (NN + 7) / 8;  // 8 warps per 256-thread block
    k_spmm<<<spmm_blocks, 256>>>(X, 0);
    k_spmm<<<spmm_blocks, 256>>>(X, 1);
    k_spmm<<<spmm_blocks, 256>>>(X, 2);

    // Fused concat + Linear
    k_gemm<<<(NN + 63) / 64, 256>>>(X, W, b, out);
}

// round 2
// speedup vs baseline: 1.0234x; 1.0234x over previous
#include <cuda_runtime.h>
#include <cuda_fp16.h>

// Problem constants (fixed by the reference)
#define NN 100000
#define EE 3200000
#define DD 128
#define NB_SCAN 98   // ceil(NN / 1024)

// ---------------- static device scratch (no allocation allowed) --------------
__device__ int    g_cnt[NN];                 // histogram counts, then scatter cursor
__device__ int    g_rptr[NN + 1];            // CSR row pointers
__device__ int    g_bsum[128];               // block sums for 2-level scan
__device__ int    g_cols[EE];                // CSR col indices (row-sorted)
__device__ float  g_vals[EE];                // CSR values (row-sorted)
// Z1, Z2, Z3 stored fp16 (accumulation always fp32)
__device__ __align__(16) __half g_Zh[3][(size_t)NN * DD];

// ---------------- CSR build ----------------

__global__ void k_zero_cnt() {
    int i = blockIdx.x * blockDim.x + threadIdx.x;
    if (i < NN) g_cnt[i] = 0;
}

__global__ void k_hist(const int* __restrict__ row) {
    int e = blockIdx.x * blockDim.x + threadIdx.x;
    if (e < EE) atomicAdd(&g_cnt[row[e]], 1);
}

// Per-block exclusive scan of counts (1024/block), emits block totals.
__global__ void k_scan1() {
    __shared__ int s[1024];
    int t = threadIdx.x;
    int i = blockIdx.x * 1024 + t;
    int v = (i < NN) ? g_cnt[i] : 0;
    s[t] = v;
    __syncthreads();
    for (int off = 1; off < 1024; off <<= 1) {
        int u = (t >= off) ? s[t - off] : 0;
        __syncthreads();
        s[t] += u;
        __syncthreads();
    }
    if (i < NN) g_rptr[i] = s[t] - v;          // exclusive within block
    if (t == 1023) g_bsum[blockIdx.x] = s[1023];
}

// Scan the 98 block sums (single block).
__global__ void k_scan2() {
    __shared__ int s[128];
    int t = threadIdx.x;
    int v = (t < NB_SCAN) ? g_bsum[t] : 0;
    s[t] = v;
    __syncthreads();
    for (int off = 1; off < 128; off <<= 1) {
        int u = (t >= off) ? s[t - off] : 0;
        __syncthreads();
        s[t] += u;
        __syncthreads();
    }
    g_bsum[t] = s[t] - v;                       // exclusive
}

// Add block offsets; seed scatter cursors; close row_ptr.
__global__ void k_scan3() {
    int i = blockIdx.x * blockDim.x + threadIdx.x;
    if (i < NN) {
        int p = g_rptr[i] + g_bsum[i >> 10];
        g_rptr[i] = p;
        g_cnt[i]  = p;
    }
    if (i == 0) g_rptr[NN] = EE;
}

__global__ void k_scatter(const int* __restrict__ row, const int* __restrict__ col,
                          const float* __restrict__ val) {
    int e = blockIdx.x * blockDim.x + threadIdx.x;
    if (e < EE) {
        int r = row[e];
        int p = atomicAdd(&g_cnt[r], 1);
        g_cols[p] = col[e];
        g_vals[p] = val[e];
    }
}

// ---------------- SpMM hop 0: X (fp32) -> Z1 (fp16) ----------------
// Warp per row; lane covers dims [lane*4, lane*4+4).
__global__ void __launch_bounds__(256) k_spmm0(const float* __restrict__ X) {
    const float4* __restrict__ Xv = (const float4*)X;
    uint2* __restrict__ Zout = (uint2*)&g_Zh[0][0];

    int w = (blockIdx.x * blockDim.x + threadIdx.x) >> 5;
    if (w >= NN) return;
    int lane = threadIdx.x & 31;

    int s = g_rptr[w], e = g_rptr[w + 1];
    float a0 = 0.f, a1 = 0.f, a2 = 0.f, a3 = 0.f;
    int i = s;
    for (; i + 4 <= e; i += 4) {
        int   c0 = g_cols[i],     c1 = g_cols[i + 1],
              c2 = g_cols[i + 2], c3 = g_cols[i + 3];
        float v0 = g_vals[i],     v1 = g_vals[i + 1],
              v2 = g_vals[i + 2], v3 = g_vals[i + 3];
        float4 z0 = Xv[c0 * 32 + lane];
        float4 z1 = Xv[c1 * 32 + lane];
        float4 z2 = Xv[c2 * 32 + lane];
        float4 z3 = Xv[c3 * 32 + lane];
        a0 += v0 * z0.x; a1 += v0 * z0.y; a2 += v0 * z0.z; a3 += v0 * z0.w;
        a0 += v1 * z1.x; a1 += v1 * z1.y; a2 += v1 * z1.z; a3 += v1 * z1.w;
        a0 += v2 * z2.x; a1 += v2 * z2.y; a2 += v2 * z2.z; a3 += v2 * z2.w;
        a0 += v3 * z3.x; a1 += v3 * z3.y; a2 += v3 * z3.z; a3 += v3 * z3.w;
    }
    for (; i < e; i++) {
        int c = g_cols[i];
        float v = g_vals[i];
        float4 z = Xv[c * 32 + lane];
        a0 += v * z.x; a1 += v * z.y; a2 += v * z.z; a3 += v * z.w;
    }
    uint2 o;
    __half2 h0 = __float22half2_rn(make_float2(a0, a1));
    __half2 h1 = __float22half2_rn(make_float2(a2, a3));
    o.x = *(unsigned int*)&h0;
    o.y = *(unsigned int*)&h1;
    Zout[w * 32 + lane] = o;
}

// ---------------- SpMM hops 1..2: Z (fp16) -> Z (fp16) ----------------
__global__ void __launch_bounds__(256) k_spmmh(int hop) {
    const uint2* __restrict__ Zin  = (const uint2*)&g_Zh[hop - 1][0];
    uint2* __restrict__       Zout = (uint2*)&g_Zh[hop][0];

    int w = (blockIdx.x * blockDim.x + threadIdx.x) >> 5;
    if (w >= NN) return;
    int lane = threadIdx.x & 31;

    int s = g_rptr[w], e = g_rptr[w + 1];
    float a0 = 0.f, a1 = 0.f, a2 = 0.f, a3 = 0.f;
    int i = s;
    for (; i + 4 <= e; i += 4) {
        int   c0 = g_cols[i],     c1 = g_cols[i + 1],
              c2 = g_cols[i + 2], c3 = g_cols[i + 3];
        float v0 = g_vals[i],     v1 = g_vals[i + 1],
              v2 = g_vals[i + 2], v3 = g_vals[i + 3];
        uint2 u0 = Zin[c0 * 32 + lane];
        uint2 u1 = Zin[c1 * 32 + lane];
        uint2 u2 = Zin[c2 * 32 + lane];
        uint2 u3 = Zin[c3 * 32 + lane];
        float2 f00 = __half22float2(*(__half2*)&u0.x), f01 = __half22float2(*(__half2*)&u0.y);
        float2 f10 = __half22float2(*(__half2*)&u1.x), f11 = __half22float2(*(__half2*)&u1.y);
        float2 f20 = __half22float2(*(__half2*)&u2.x), f21 = __half22float2(*(__half2*)&u2.y);
        float2 f30 = __half22float2(*(__half2*)&u3.x), f31 = __half22float2(*(__half2*)&u3.y);
        a0 += v0 * f00.x; a1 += v0 * f00.y; a2 += v0 * f01.x; a3 += v0 * f01.y;
        a0 += v1 * f10.x; a1 += v1 * f10.y; a2 += v1 * f11.x; a3 += v1 * f11.y;
        a0 += v2 * f20.x; a1 += v2 * f20.y; a2 += v2 * f21.x; a3 += v2 * f21.y;
        a0 += v3 * f30.x; a1 += v3 * f30.y; a2 += v3 * f31.x; a3 += v3 * f31.y;
    }
    for (; i < e; i++) {
        int c = g_cols[i];
        float v = g_vals[i];
        uint2 u = Zin[c * 32 + lane];
        float2 f0 = __half22float2(*(__half2*)&u.x), f1 = __half22float2(*(__half2*)&u.y);
        a0 += v * f0.x; a1 += v * f0.y; a2 += v * f1.x; a3 += v * f1.y;
    }
    uint2 o;
    __half2 h0 = __float22half2_rn(make_float2(a0, a1));
    __half2 h1 = __float22half2_rn(make_float2(a2, a3));
    o.x = *(unsigned int*)&h0;
    o.y = *(unsigned int*)&h1;
    Zout[w * 32 + lane] = o;
}

// ---------------- GEMM segment kernels ----------------
// out[i,j] (+)= H[i,:128] @ Wseg[:,j]   64-row x 128-col blocks, 8x4 reg tile.

// Segment 0: H = X (fp32); writes out with bias.
__global__ void __launch_bounds__(256) k_gemm_x(const float* __restrict__ X,
                                                const float* __restrict__ W,
                                                const float* __restrict__ bias,
                                                float* __restrict__ out) {
    __shared__ float sH[64][36];
    __shared__ float sW[32][128];
    int tid = threadIdx.x;
    int tx = tid & 31, ty = tid >> 5;
    int rowBase = blockIdx.x * 64;

    float acc[8][4];
#pragma unroll
    for (int r = 0; r < 8; r++)
#pragma unroll
        for (int c = 0; c < 4; c++) acc[r][c] = 0.f;

    for (int kk = 0; kk < 128; kk += 32) {
#pragma unroll
        for (int u = 0; u < 2; u++) {
            int f = tid + u * 256;
            int r = f >> 3;
            int ko = (f & 7) * 4;
            int grow = rowBase + r;
            float4 hv = make_float4(0.f, 0.f, 0.f, 0.f);
            if (grow < NN)
                hv = *(const float4*)&X[(size_t)grow * DD + kk + ko];
            *(float4*)&sH[r][ko] = hv;
        }
#pragma unroll
        for (int u = 0; u < 4; u++) {
            int f = tid + u * 256;
            int k = f >> 5;
            int j = (f & 31) * 4;
            *(float4*)&sW[k][j] = *(const float4*)&W[(size_t)(kk + k) * DD + j];
        }
        __syncthreads();
#pragma unroll
        for (int k = 0; k < 32; k++) {
            float4 wv = *(float4*)&sW[k][tx * 4];
#pragma unroll
            for (int rr = 0; rr < 8; rr++) {
                float h = sH[ty * 8 + rr][k];
                acc[rr][0] += h * wv.x;
                acc[rr][1] += h * wv.y;
                acc[rr][2] += h * wv.z;
                acc[rr][3] += h * wv.w;
            }
        }
        __syncthreads();
    }

    float4 bb = *(const float4*)&bias[tx * 4];
#pragma unroll
    for (int rr = 0; rr < 8; rr++) {
        int grow = rowBase + ty * 8 + rr;
        if (grow < NN) {
            float4 o;
            o.x = acc[rr][0] + bb.x;
            o.y = acc[rr][1] + bb.y;
            o.z = acc[rr][2] + bb.z;
            o.w = acc[rr][3] + bb.w;
            *(float4*)&out[(size_t)grow * DD + tx * 4] = o;
        }
    }
}

// Segments 1..3: H = g_Zh[zi] (fp16); accumulates into out.
__global__ void __launch_bounds__(256) k_gemm_h(int zi,
                                                const float* __restrict__ W,
                                                float* __restrict__ out) {
    __shared__ float sH[64][36];
    __shared__ float sW[32][128];
    int tid = threadIdx.x;
    int tx = tid & 31, ty = tid >> 5;
    int rowBase = blockIdx.x * 64;
    const uint2* __restrict__ Z = (const uint2*)&g_Zh[zi][0];

    float acc[8][4];
#pragma unroll
    for (int r = 0; r < 8; r++)
#pragma unroll
        for (int c = 0; c < 4; c++) acc[r][c] = 0.f;

    for (int kk = 0; kk < 128; kk += 32) {
#pragma unroll
        for (int u = 0; u < 2; u++) {
            int f = tid + u * 256;
            int r = f >> 3;
            int ko = (f & 7) * 4;
            int grow = rowBase + r;
            float4 hv = make_float4(0.f, 0.f, 0.f, 0.f);
            if (grow < NN) {
                uint2 uu = Z[(size_t)grow * 32 + ((kk + ko) >> 2)];
                float2 fa = __half22float2(*(__half2*)&uu.x);
                float2 fb = __half22float2(*(__half2*)&uu.y);
                hv = make_float4(fa.x, fa.y, fb.x, fb.y);
            }
            *(float4*)&sH[r][ko] = hv;
        }
#pragma unroll
        for (int u = 0; u < 4; u++) {
            int f = tid + u * 256;
            int k = f >> 5;
            int j = (f & 31) * 4;
            *(float4*)&sW[k][j] = *(const float4*)&W[(size_t)(kk + k) * DD + j];
        }
        __syncthreads();
#pragma unroll
        for (int k = 0; k < 32; k++) {
            float4 wv = *(float4*)&sW[k][tx * 4];
#pragma unroll
            for (int rr = 0; rr < 8; rr++) {
                float h = sH[ty * 8 + rr][k];
                acc[rr][0] += h * wv.x;
                acc[rr][1] += h * wv.y;
                acc[rr][2] += h * wv.z;
                acc[rr][3] += h * wv.w;
            }
        }
        __syncthreads();
    }

#pragma unroll
    for (int rr = 0; rr < 8; rr++) {
        int grow = rowBase + ty * 8 + rr;
        if (grow < NN) {
            float4 o = *(float4*)&out[(size_t)grow * DD + tx * 4];
            o.x += acc[rr][0];
            o.y += acc[rr][1];
            o.z += acc[rr][2];
            o.w += acc[rr][3];
            *(float4*)&out[(size_t)grow * DD + tx * 4] = o;
        }
    }
}

// ---------------- launch ----------------
static cudaStream_t s_side = nullptr;
static cudaEvent_t s_evFork, s_evZ1, s_evZ2, s_evZ3, s_evJoin;

extern "C" void kernel_launch(void* const* d_in, const int* in_sizes, int n_in,
                              void* d_out, int out_size) {
    const float* X  = (const float*)d_in[0];
    const int*   Ar = (const int*)d_in[1];
    const int*   Ac = (const int*)d_in[2];
    const float* Av = (const float*)d_in[3];
    const float* W  = (const float*)d_in[4];
    const float* b  = (const float*)d_in[5];
    float* out = (float*)d_out;

    if (!s_side) {
        cudaStreamCreateWithFlags(&s_side, cudaStreamNonBlocking);
        cudaEventCreateWithFlags(&s_evFork, cudaEventDisableTiming);
        cudaEventCreateWithFlags(&s_evZ1, cudaEventDisableTiming);
        cudaEventCreateWithFlags(&s_evZ2, cudaEventDisableTiming);
        cudaEventCreateWithFlags(&s_evZ3, cudaEventDisableTiming);
        cudaEventCreateWithFlags(&s_evJoin, cudaEventDisableTiming);
    }

    int gemm_blocks = (NN + 63) / 64;
    int spmm_blocks = (NN + 7) / 8;  // 8 warps per 256-thread block

    // Fork side stream: seg0 GEMM (X @ W0 + b) depends only on X.
    cudaEventRecord(s_evFork, 0);
    cudaStreamWaitEvent(s_side, s_evFork, 0);
    k_gemm_x<<<gemm_blocks, 256, 0, s_side>>>(X, W, b, out);

    // CSR build (default stream)
    k_zero_cnt<<<(NN + 255) / 256, 256>>>();
    k_hist<<<(EE + 255) / 256, 256>>>(Ar);
    k_scan1<<<NB_SCAN, 1024>>>();
    k_scan2<<<1, 128>>>();
    k_scan3<<<(NN + 255) / 256, 256>>>();
    k_scatter<<<(EE + 255) / 256, 256>>>(Ar, Ac, Av);

    // Hop 1, then stream seg1 GEMM on the side while hop 2 runs, etc.
    k_spmm0<<<spmm_blocks, 256>>>(X);
    cudaEventRecord(s_evZ1, 0);
    cudaStreamWaitEvent(s_side, s_evZ1, 0);
    k_gemm_h<<<gemm_blocks, 256, 0, s_side>>>(0, W + 1 * DD * DD, out);

    k_spmmh<<<spmm_blocks, 256>>>(1);
    cudaEventRecord(s_evZ2, 0);
    cudaStreamWaitEvent(s_side, s_evZ2, 0);
    k_gemm_h<<<gemm_blocks, 256, 0, s_side>>>(1, W + 2 * DD * DD, out);

    k_spmmh<<<spmm_blocks, 256>>>(2);
    cudaEventRecord(s_evZ3, 0);
    cudaStreamWaitEvent(s_side, s_evZ3, 0);
    k_gemm_h<<<gemm_blocks, 256, 0, s_side>>>(2, W + 3 * DD * DD, out);

    // Join side stream back into the captured (default) stream.
    cudaEventRecord(s_evJoin, s_side);
    cudaStreamWaitEvent(0, s_evJoin, 0);
}

// round 4
// speedup vs baseline: 1.6286x; 1.5914x over previous
#include <cuda_runtime.h>
#include <cuda_fp16.h>
#include <cstdint>

// Problem constants (fixed by the reference)
#define NN 100000
#define EE 3200000
#define DD 128
#define NNP 100096           // padded row count for Z buffers (rows >= NN stay zero)
#define NB_SCAN 98           // ceil(NN / 1024)

// ---------------- static device scratch (no allocation allowed) --------------
__device__ int    g_cnt[NN];
__device__ int    g_rptr[NN + 1];
__device__ int    g_bsum[128];
__device__ int    g_cols[EE];
__device__ float  g_vals[EE];
// Z1..Z3 fp16, padded rows NN..NNP-1 never written (stay zero from module init)
__device__ __align__(16) __half g_Zh[3][(size_t)NNP * DD];
// W transposed to [seg][n][k], fp16
__device__ __align__(16) __half g_Wt[4 * DD * DD];

// ---------------- conversions ----------------
__global__ void k_wcast(const float* __restrict__ W) {
    int idx = blockIdx.x * blockDim.x + threadIdx.x;   // [seg][n][k]
    if (idx >= 4 * DD * DD) return;
    int seg = idx >> 14;
    int rem = idx & 16383;
    int n = rem >> 7;
    int k = rem & 127;
    g_Wt[idx] = __float2half(W[(size_t)(seg * DD + k) * DD + n]);
}

// ---------------- CSR build ----------------
__global__ void k_zero_cnt() {
    int i = blockIdx.x * blockDim.x + threadIdx.x;
    if (i < NN) g_cnt[i] = 0;
}

__global__ void k_hist(const int* __restrict__ row) {
    int e = blockIdx.x * blockDim.x + threadIdx.x;
    if (e < EE) atomicAdd(&g_cnt[row[e]], 1);
}

__global__ void k_scan1() {
    __shared__ int s[1024];
    int t = threadIdx.x;
    int i = blockIdx.x * 1024 + t;
    int v = (i < NN) ? g_cnt[i] : 0;
    s[t] = v;
    __syncthreads();
    for (int off = 1; off < 1024; off <<= 1) {
        int u = (t >= off) ? s[t - off] : 0;
        __syncthreads();
        s[t] += u;
        __syncthreads();
    }
    if (i < NN) g_rptr[i] = s[t] - v;
    if (t == 1023) g_bsum[blockIdx.x] = s[1023];
}

__global__ void k_scan2() {
    __shared__ int s[128];
    int t = threadIdx.x;
    int v = (t < NB_SCAN) ? g_bsum[t] : 0;
    s[t] = v;
    __syncthreads();
    for (int off = 1; off < 128; off <<= 1) {
        int u = (t >= off) ? s[t - off] : 0;
        __syncthreads();
        s[t] += u;
        __syncthreads();
    }
    g_bsum[t] = s[t] - v;
}

__global__ void k_scan3() {
    int i = blockIdx.x * blockDim.x + threadIdx.x;
    if (i < NN) {
        int p = g_rptr[i] + g_bsum[i >> 10];
        g_rptr[i] = p;
        g_cnt[i]  = p;
    }
    if (i == 0) g_rptr[NN] = EE;
}

__global__ void k_scatter(const int* __restrict__ row, const int* __restrict__ col,
                          const float* __restrict__ val) {
    int e = blockIdx.x * blockDim.x + threadIdx.x;
    if (e < EE) {
        int r = row[e];
        int p = atomicAdd(&g_cnt[r], 1);
        g_cols[p] = col[e];
        g_vals[p] = val[e];
    }
}

// ---------------- SpMM hop 0: X (fp32) -> Z1 (fp16) ----------------
__global__ void __launch_bounds__(256) k_spmm0(const float* __restrict__ X) {
    const float4* __restrict__ Xv = (const float4*)X;
    uint2* __restrict__ Zout = (uint2*)&g_Zh[0][0];

    int w = (blockIdx.x * blockDim.x + threadIdx.x) >> 5;
    if (w >= NN) return;
    int lane = threadIdx.x & 31;

    int s = g_rptr[w], e = g_rptr[w + 1];
    float a0 = 0.f, a1 = 0.f, a2 = 0.f, a3 = 0.f;
    int i = s;
    for (; i + 4 <= e; i += 4) {
        int   c0 = g_cols[i],     c1 = g_cols[i + 1],
              c2 = g_cols[i + 2], c3 = g_cols[i + 3];
        float v0 = g_vals[i],     v1 = g_vals[i + 1],
              v2 = g_vals[i + 2], v3 = g_vals[i + 3];
        float4 z0 = Xv[(size_t)c0 * 32 + lane];
        float4 z1 = Xv[(size_t)c1 * 32 + lane];
        float4 z2 = Xv[(size_t)c2 * 32 + lane];
        float4 z3 = Xv[(size_t)c3 * 32 + lane];
        a0 += v0 * z0.x; a1 += v0 * z0.y; a2 += v0 * z0.z; a3 += v0 * z0.w;
        a0 += v1 * z1.x; a1 += v1 * z1.y; a2 += v1 * z1.z; a3 += v1 * z1.w;
        a0 += v2 * z2.x; a1 += v2 * z2.y; a2 += v2 * z2.z; a3 += v2 * z2.w;
        a0 += v3 * z3.x; a1 += v3 * z3.y; a2 += v3 * z3.z; a3 += v3 * z3.w;
    }
    for (; i < e; i++) {
        int c = g_cols[i];
        float v = g_vals[i];
        float4 z = Xv[(size_t)c * 32 + lane];
        a0 += v * z.x; a1 += v * z.y; a2 += v * z.z; a3 += v * z.w;
    }
    uint2 o;
    __half2 h0 = __float22half2_rn(make_float2(a0, a1));
    __half2 h1 = __float22half2_rn(make_float2(a2, a3));
    o.x = *(unsigned int*)&h0;
    o.y = *(unsigned int*)&h1;
    Zout[(size_t)w * 32 + lane] = o;
}

// ---------------- SpMM hops 1..2: fp16 -> fp16 ----------------
__global__ void __launch_bounds__(256) k_spmmh(int hop) {
    const uint2* __restrict__ Zin  = (const uint2*)&g_Zh[hop - 1][0];
    uint2* __restrict__       Zout = (uint2*)&g_Zh[hop][0];

    int w = (blockIdx.x * blockDim.x + threadIdx.x) >> 5;
    if (w >= NN) return;
    int lane = threadIdx.x & 31;

    int s = g_rptr[w], e = g_rptr[w + 1];
    float a0 = 0.f, a1 = 0.f, a2 = 0.f, a3 = 0.f;
    int i = s;
    for (; i + 8 <= e; i += 8) {
        int   c[8];
        float v[8];
#pragma unroll
        for (int u = 0; u < 8; u++) { c[u] = g_cols[i + u]; v[u] = g_vals[i + u]; }
        uint2 z[8];
#pragma unroll
        for (int u = 0; u < 8; u++) z[u] = Zin[(size_t)c[u] * 32 + lane];
#pragma unroll
        for (int u = 0; u < 8; u++) {
            float2 f0 = __half22float2(*(__half2*)&z[u].x);
            float2 f1 = __half22float2(*(__half2*)&z[u].y);
            a0 += v[u] * f0.x; a1 += v[u] * f0.y;
            a2 += v[u] * f1.x; a3 += v[u] * f1.y;
        }
    }
    for (; i < e; i++) {
        int cc = g_cols[i];
        float vv = g_vals[i];
        uint2 z = Zin[(size_t)cc * 32 + lane];
        float2 f0 = __half22float2(*(__half2*)&z.x);
        float2 f1 = __half22float2(*(__half2*)&z.y);
        a0 += vv * f0.x; a1 += vv * f0.y; a2 += vv * f1.x; a3 += vv * f1.y;
    }
    uint2 o;
    __half2 h0 = __float22half2_rn(make_float2(a0, a1));
    __half2 h1 = __float22half2_rn(make_float2(a2, a3));
    o.x = *(unsigned int*)&h0;
    o.y = *(unsigned int*)&h1;
    Zout[(size_t)w * 32 + lane] = o;
}

// ---------------- Fused 4-segment tensor-core GEMM ----------------
// out[i,j] = sum_seg H_seg[i,:] @ Wt[seg][j,:] + b[j]
// Block: 64 rows x 128 cols, 256 threads. Warp tile 32x32. kc = 64. Static smem.
#define KC 64
#define SAS 72    // sA k-stride in halfs (64 + 8 pad)
#define SBS 72    // sB k-stride

__global__ void __launch_bounds__(256) k_gemm(const float* __restrict__ X,
                                              const float* __restrict__ bias,
                                              float* __restrict__ out) {
    __shared__ __half sA[64 * SAS];     // [row][k]
    __shared__ __half sB[128 * SBS];    // [n][k]

    int tid  = threadIdx.x;
    int wid  = tid >> 5;
    int lane = tid & 31;
    int wm = wid & 1;          // row group: rows wm*32
    int wn = wid >> 1;         // col group: cols wn*32
    int rowBase = blockIdx.x * 64;

    int lr = lane >> 2;        // 0..7
    int lc = lane & 3;         // 0..3

    float acc[2][4][4];
#pragma unroll
    for (int mi = 0; mi < 2; mi++)
#pragma unroll
        for (int ni = 0; ni < 4; ni++)
#pragma unroll
            for (int q = 0; q < 4; q++) acc[mi][ni][q] = 0.f;

    for (int seg = 0; seg < 4; seg++) {
        const __half* __restrict__ zsrc = (seg == 0) ? (const __half*)0 : &g_Zh[seg - 1][0];
        const __half* __restrict__ wsrc = &g_Wt[seg * DD * DD];
        for (int kk = 0; kk < DD; kk += KC) {
            // Stage A: 64 rows x 64 k = 2048 half2; 8 per thread.
            if (seg == 0) {
#pragma unroll
                for (int u = 0; u < 8; u++) {
                    int idx = tid + u * 256;
                    int r  = idx >> 5;           // 0..63
                    int k2 = idx & 31;           // half2 within chunk
                    int grow = rowBase + r;
                    float2 f = make_float2(0.f, 0.f);
                    if (grow < NN)
                        f = *(const float2*)&X[(size_t)grow * DD + kk + k2 * 2];
                    __half2 h = __float22half2_rn(f);
                    *(__half2*)&sA[r * SAS + k2 * 2] = h;
                }
            } else {
#pragma unroll
                for (int u = 0; u < 8; u++) {
                    int idx = tid + u * 256;
                    int r  = idx >> 5;
                    int k2 = idx & 31;
                    // padded rows < NNP are zero-initialized and never written
                    unsigned v = *(const unsigned*)&zsrc[(size_t)(rowBase + r) * DD + kk + k2 * 2];
                    *(unsigned*)&sA[r * SAS + k2 * 2] = v;
                }
            }
            // Stage B: 128 n x 64 k halfs = 1024 uint4; 4 per thread.
#pragma unroll
            for (int u = 0; u < 4; u++) {
                int idx = tid + u * 256;
                int n  = idx >> 3;               // 0..127
                int k8 = (idx & 7) * 8;
                uint4 v = *(const uint4*)&wsrc[n * DD + kk + k8];
                *(uint4*)&sB[n * SBS + k8] = v;
            }
            __syncthreads();

#pragma unroll
            for (int ks = 0; ks < KC / 16; ks++) {
                int k0 = ks * 16 + lc * 2;
                unsigned b0[4], b1[4];
#pragma unroll
                for (int ni = 0; ni < 4; ni++) {
                    int n = wn * 32 + ni * 8 + lr;
                    b0[ni] = *(const unsigned*)&sB[n * SBS + k0];
                    b1[ni] = *(const unsigned*)&sB[n * SBS + k0 + 8];
                }
#pragma unroll
                for (int mi = 0; mi < 2; mi++) {
                    int r = wm * 32 + mi * 16 + lr;
                    unsigned a0 = *(const unsigned*)&sA[r * SAS + k0];
                    unsigned a1 = *(const unsigned*)&sA[(r + 8) * SAS + k0];
                    unsigned a2 = *(const unsigned*)&sA[r * SAS + k0 + 8];
                    unsigned a3 = *(const unsigned*)&sA[(r + 8) * SAS + k0 + 8];
#pragma unroll
                    for (int ni = 0; ni < 4; ni++) {
                        asm volatile(
                            "mma.sync.aligned.m16n8k16.row.col.f32.f16.f16.f32 "
                            "{%0,%1,%2,%3}, {%4,%5,%6,%7}, {%8,%9}, {%0,%1,%2,%3};"
                            : "+f"(acc[mi][ni][0]), "+f"(acc[mi][ni][1]),
                              "+f"(acc[mi][ni][2]), "+f"(acc[mi][ni][3])
                            : "r"(a0), "r"(a1), "r"(a2), "r"(a3),
                              "r"(b0[ni]), "r"(b1[ni]));
                    }
                }
            }
            __syncthreads();
        }
    }

    // Epilogue: add bias, store fp32.
#pragma unroll
    for (int ni = 0; ni < 4; ni++) {
        int col = wn * 32 + ni * 8 + lc * 2;
        float2 bb = *(const float2*)&bias[col];
#pragma unroll
        for (int mi = 0; mi < 2; mi++) {
            int r0 = rowBase + wm * 32 + mi * 16 + lr;
            if (r0 < NN) {
                float2 o0 = make_float2(acc[mi][ni][0] + bb.x, acc[mi][ni][1] + bb.y);
                *(float2*)&out[(size_t)r0 * DD + col] = o0;
            }
            int r1 = r0 + 8;
            if (r1 < NN) {
                float2 o1 = make_float2(acc[mi][ni][2] + bb.x, acc[mi][ni][3] + bb.y);
                *(float2*)&out[(size_t)r1 * DD + col] = o1;
            }
        }
    }
}

// ---------------- launch: kernels only, single stream ----------------
extern "C" void kernel_launch(void* const* d_in, const int* in_sizes, int n_in,
                              void* d_out, int out_size) {
    const float* X  = (const float*)d_in[0];
    const int*   Ar = (const int*)d_in[1];
    const int*   Ac = (const int*)d_in[2];
    const float* Av = (const float*)d_in[3];
    const float* W  = (const float*)d_in[4];
    const float* b  = (const float*)d_in[5];
    float* out = (float*)d_out;

    // W -> fp16 transposed
    k_wcast<<<(4 * DD * DD + 255) / 256, 256>>>(W);

    // CSR build
    k_zero_cnt<<<(NN + 255) / 256, 256>>>();
    k_hist<<<(EE + 255) / 256, 256>>>(Ar);
    k_scan1<<<NB_SCAN, 1024>>>();
    k_scan2<<<1, 128>>>();
    k_scan3<<<(NN + 255) / 256, 256>>>();
    k_scatter<<<(EE + 255) / 256, 256>>>(Ar, Ac, Av);

    // 3 SpMM hops
    int spmm_blocks = (NN * 32 + 255) / 256;
    k_spmm0<<<spmm_blocks, 256>>>(X);
    k_spmmh<<<spmm_blocks, 256>>>(1);
    k_spmmh<<<spmm_blocks, 256>>>(2);

    // Fused 4-segment tensor-core GEMM + bias
    k_gemm<<<(NN + 63) / 64, 256>>>(X, b, out);
}

// round 8
// speedup vs baseline: 1.6362x; 1.0046x over previous
#include <cuda_runtime.h>
#include <cuda_fp16.h>
#include <cstdint>

// Problem constants (fixed by the reference)
#define NN 100000
#define EE 3200000
#define DD 128
#define NNP 100096           // padded row count (rows >= NN stay zero)
#define NB_SCAN 98           // ceil(NN / 1024)

// ---------------- static device scratch ----------------
// RULE (learned rounds 3/5/6/7): g_* symbols are referenced ONLY inside device
// code. Host code passes int selectors, never &g_*.
__device__ int    g_cnt[NN];
__device__ int    g_rptr[NN + 1];
__device__ int    g_bsum[128];
__device__ int    g_cols[EE];
__device__ float  g_vals[EE];
// Z buffers, fp16. g_Zh[2] doubles as fp16-X storage before hop 2 overwrites it:
//   xcast: X -> g_Zh[2]; hop0: g_Zh[2]->g_Zh[0]; hop1: g_Zh[0]->g_Zh[1];
//   hop2: g_Zh[1]->g_Zh[2]  (Xh dead by then).
__device__ __align__(16) __half g_Zh[3][(size_t)NNP * DD];
// W transposed to [seg][n][k], fp16
__device__ __align__(16) __half g_Wt[4 * DD * DD];

// ---------------- conversions ----------------
__global__ void k_wcast(const float* __restrict__ W) {
    int idx = blockIdx.x * blockDim.x + threadIdx.x;   // [seg][n][k]
    if (idx >= 4 * DD * DD) return;
    int seg = idx >> 14;
    int rem = idx & 16383;
    int n = rem >> 7;
    int k = rem & 127;
    g_Wt[idx] = __float2half(W[(size_t)(seg * DD + k) * DD + n]);
}

// X (fp32) -> fp16 into g_Zh[2]'s storage; zero-pads rows NN..NNP-1.
__global__ void k_xcast(const float* __restrict__ X) {
    int idx = blockIdx.x * blockDim.x + threadIdx.x;   // half2 index
    if (idx >= NNP * (DD / 2)) return;
    int j = idx * 2;
    __half2 h;
    if (j < NN * DD) {
        float2 f = *(const float2*)&X[j];
        h = __float22half2_rn(f);
    } else {
        h = __float2half2_rn(0.f);
    }
    *(__half2*)&g_Zh[2][j] = h;
}

// ---------------- CSR build (identical to round-4 passing version) ----------
__global__ void k_zero_cnt() {
    int i = blockIdx.x * blockDim.x + threadIdx.x;
    if (i < NN) g_cnt[i] = 0;
}

__global__ void k_hist(const int* __restrict__ row) {
    int e = blockIdx.x * blockDim.x + threadIdx.x;
    if (e < EE) atomicAdd(&g_cnt[row[e]], 1);
}

__global__ void k_scan1() {
    __shared__ int s[1024];
    int t = threadIdx.x;
    int i = blockIdx.x * 1024 + t;
    int v = (i < NN) ? g_cnt[i] : 0;
    s[t] = v;
    __syncthreads();
    for (int off = 1; off < 1024; off <<= 1) {
        int u = (t >= off) ? s[t - off] : 0;
        __syncthreads();
        s[t] += u;
        __syncthreads();
    }
    if (i < NN) g_rptr[i] = s[t] - v;
    if (t == 1023) g_bsum[blockIdx.x] = s[1023];
}

__global__ void k_scan2() {
    __shared__ int s[128];
    int t = threadIdx.x;
    int v = (t < NB_SCAN) ? g_bsum[t] : 0;
    s[t] = v;
    __syncthreads();
    for (int off = 1; off < 128; off <<= 1) {
        int u = (t >= off) ? s[t - off] : 0;
        __syncthreads();
        s[t] += u;
        __syncthreads();
    }
    g_bsum[t] = s[t] - v;
}

__global__ void k_scan3() {
    int i = blockIdx.x * blockDim.x + threadIdx.x;
    if (i < NN) {
        int p = g_rptr[i] + g_bsum[i >> 10];
        g_rptr[i] = p;
        g_cnt[i]  = p;
    }
    if (i == 0) g_rptr[NN] = EE;
}

__global__ void k_scatter(const int* __restrict__ row, const int* __restrict__ col,
                          const float* __restrict__ val) {
    int e = blockIdx.x * blockDim.x + threadIdx.x;
    if (e < EE) {
        int r = row[e];
        int p = atomicAdd(&g_cnt[r], 1);
        g_cols[p] = col[e];
        g_vals[p] = val[e];
    }
}

// ---------------- SpMM: warp per row, fp16 in/out, fp32 accum ----------------
// Buffer indices resolved in DEVICE code (int selectors from host).
__global__ void __launch_bounds__(256) k_spmm(int srcIdx, int dstIdx) {
    const uint2* __restrict__ Zin  = (const uint2*)&g_Zh[srcIdx][0];
    uint2* __restrict__       Zout = (uint2*)&g_Zh[dstIdx][0];

    int w = (blockIdx.x * blockDim.x + threadIdx.x) >> 5;
    if (w >= NN) return;
    int lane = threadIdx.x & 31;

    int s = g_rptr[w], e = g_rptr[w + 1];
    float a0 = 0.f, a1 = 0.f, a2 = 0.f, a3 = 0.f;
    int i = s;
    for (; i + 8 <= e; i += 8) {
        int   c[8];
        float v[8];
#pragma unroll
        for (int u = 0; u < 8; u++) { c[u] = g_cols[i + u]; v[u] = g_vals[i + u]; }
        uint2 z[8];
#pragma unroll
        for (int u = 0; u < 8; u++) z[u] = Zin[(size_t)c[u] * 32 + lane];
#pragma unroll
        for (int u = 0; u < 8; u++) {
            float2 f0 = __half22float2(*(__half2*)&z[u].x);
            float2 f1 = __half22float2(*(__half2*)&z[u].y);
            a0 += v[u] * f0.x; a1 += v[u] * f0.y;
            a2 += v[u] * f1.x; a3 += v[u] * f1.y;
        }
    }
    for (; i < e; i++) {
        int cc = g_cols[i];
        float vv = g_vals[i];
        uint2 z = Zin[(size_t)cc * 32 + lane];
        float2 f0 = __half22float2(*(__half2*)&z.x);
        float2 f1 = __half22float2(*(__half2*)&z.y);
        a0 += vv * f0.x; a1 += vv * f0.y; a2 += vv * f1.x; a3 += vv * f1.y;
    }
    uint2 o;
    __half2 h0 = __float22half2_rn(make_float2(a0, a1));
    __half2 h1 = __float22half2_rn(make_float2(a2, a3));
    o.x = *(unsigned int*)&h0;
    o.y = *(unsigned int*)&h1;
    Zout[(size_t)w * 32 + lane] = o;
}

// ---------------- Fused 4-segment tensor-core GEMM (round-4 proven) ----------
// out[i,j] = sum_seg H_seg[i,:] @ Wt[seg][j,:] + b[j]
// seg 0 stages from fp32 X directly; segs 1..3 from g_Zh (device-side symbols).
#define KC 64
#define SAS 72
#define SBS 72

__global__ void __launch_bounds__(256) k_gemm(const float* __restrict__ X,
                                              const float* __restrict__ bias,
                                              float* __restrict__ out) {
    __shared__ __half sA[64 * SAS];
    __shared__ __half sB[128 * SBS];

    int tid  = threadIdx.x;
    int wid  = tid >> 5;
    int lane = tid & 31;
    int wm = wid & 1;
    int wn = wid >> 1;
    int rowBase = blockIdx.x * 64;

    int lr = lane >> 2;
    int lc = lane & 3;

    float acc[2][4][4];
#pragma unroll
    for (int mi = 0; mi < 2; mi++)
#pragma unroll
        for (int ni = 0; ni < 4; ni++)
#pragma unroll
            for (int q = 0; q < 4; q++) acc[mi][ni][q] = 0.f;

    for (int seg = 0; seg < 4; seg++) {
        const __half* __restrict__ zsrc = (seg == 0) ? (const __half*)0 : &g_Zh[seg - 1][0];
        const __half* __restrict__ wsrc = &g_Wt[seg * DD * DD];
        for (int kk = 0; kk < DD; kk += KC) {
            // Stage A: 64 rows x 64 k = 2048 half2; 8 per thread.
            if (seg == 0) {
#pragma unroll
                for (int u = 0; u < 8; u++) {
                    int idx = tid + u * 256;
                    int r  = idx >> 5;           // 0..63
                    int k2 = idx & 31;
                    int grow = rowBase + r;
                    float2 f = make_float2(0.f, 0.f);
                    if (grow < NN)
                        f = *(const float2*)&X[(size_t)grow * DD + kk + k2 * 2];
                    __half2 h = __float22half2_rn(f);
                    *(__half2*)&sA[r * SAS + k2 * 2] = h;
                }
            } else {
#pragma unroll
                for (int u = 0; u < 8; u++) {
                    int idx = tid + u * 256;
                    int r  = idx >> 5;
                    int k2 = idx & 31;
                    unsigned v = *(const unsigned*)&zsrc[(size_t)(rowBase + r) * DD + kk + k2 * 2];
                    *(unsigned*)&sA[r * SAS + k2 * 2] = v;
                }
            }
            // Stage B: 128 n x 64 k halfs = 1024 uint4; 4 per thread.
#pragma unroll
            for (int u = 0; u < 4; u++) {
                int idx = tid + u * 256;
                int n  = idx >> 3;
                int k8 = (idx & 7) * 8;
                uint4 v = *(const uint4*)&wsrc[n * DD + kk + k8];
                *(uint4*)&sB[n * SBS + k8] = v;
            }
            __syncthreads();

#pragma unroll
            for (int ks = 0; ks < KC / 16; ks++) {
                int k0 = ks * 16 + lc * 2;
                unsigned b0[4], b1[4];
#pragma unroll
                for (int ni = 0; ni < 4; ni++) {
                    int n = wn * 32 + ni * 8 + lr;
                    b0[ni] = *(const unsigned*)&sB[n * SBS + k0];
                    b1[ni] = *(const unsigned*)&sB[n * SBS + k0 + 8];
                }
#pragma unroll
                for (int mi = 0; mi < 2; mi++) {
                    int r = wm * 32 + mi * 16 + lr;
                    unsigned a0 = *(const unsigned*)&sA[r * SAS + k0];
                    unsigned a1 = *(const unsigned*)&sA[(r + 8) * SAS + k0];
                    unsigned a2 = *(const unsigned*)&sA[r * SAS + k0 + 8];
                    unsigned a3 = *(const unsigned*)&sA[(r + 8) * SAS + k0 + 8];
#pragma unroll
                    for (int ni = 0; ni < 4; ni++) {
                        asm volatile(
                            "mma.sync.aligned.m16n8k16.row.col.f32.f16.f16.f32 "
                            "{%0,%1,%2,%3}, {%4,%5,%6,%7}, {%8,%9}, {%0,%1,%2,%3};"
                            : "+f"(acc[mi][ni][0]), "+f"(acc[mi][ni][1]),
                              "+f"(acc[mi][ni][2]), "+f"(acc[mi][ni][3])
                            : "r"(a0), "r"(a1), "r"(a2), "r"(a3),
                              "r"(b0[ni]), "r"(b1[ni]));
                    }
                }
            }
            __syncthreads();
        }
    }

    // Epilogue: add bias, store fp32.
#pragma unroll
    for (int ni = 0; ni < 4; ni++) {
        int col = wn * 32 + ni * 8 + lc * 2;
        float2 bb = *(const float2*)&bias[col];
#pragma unroll
        for (int mi = 0; mi < 2; mi++) {
            int r0 = rowBase + wm * 32 + mi * 16 + lr;
            if (r0 < NN) {
                float2 o0 = make_float2(acc[mi][ni][0] + bb.x, acc[mi][ni][1] + bb.y);
                *(float2*)&out[(size_t)r0 * DD + col] = o0;
            }
            int r1 = r0 + 8;
            if (r1 < NN) {
                float2 o1 = make_float2(acc[mi][ni][2] + bb.x, acc[mi][ni][3] + bb.y);
                *(float2*)&out[(size_t)r1 * DD + col] = o1;
            }
        }
    }
}

// ---------------- launch: kernels only; NO g_* symbols referenced here -------
extern "C" void kernel_launch(void* const* d_in, const int* in_sizes, int n_in,
                              void* d_out, int out_size) {
    const float* X  = (const float*)d_in[0];
    const int*   Ar = (const int*)d_in[1];
    const int*   Ac = (const int*)d_in[2];
    const float* Av = (const float*)d_in[3];
    const float* W  = (const float*)d_in[4];
    const float* b  = (const float*)d_in[5];
    float* out = (float*)d_out;

    // fp16 conversions (Xh lives in g_Zh[2] until hop 2 overwrites it)
    k_wcast<<<(4 * DD * DD + 255) / 256, 256>>>(W);
    k_xcast<<<(NNP * (DD / 2) + 255) / 256, 256>>>(X);

    // CSR build
    k_zero_cnt<<<(NN + 255) / 256, 256>>>();
    k_hist<<<(EE + 255) / 256, 256>>>(Ar);
    k_scan1<<<NB_SCAN, 1024>>>();
    k_scan2<<<1, 128>>>();
    k_scan3<<<(NN + 255) / 256, 256>>>();
    k_scatter<<<(EE + 255) / 256, 256>>>(Ar, Ac, Av);

    // 3 SpMM hops (buffer indices resolved device-side)
    int spmm_blocks = (NN * 32 + 255) / 256;
    k_spmm<<<spmm_blocks, 256>>>(2, 0);  // Xh -> Z1
    k_spmm<<<spmm_blocks, 256>>>(0, 1);  // Z1 -> Z2
    k_spmm<<<spmm_blocks, 256>>>(1, 2);  // Z2 -> Z3 (overwrites dead Xh)

    // Fused 4-segment tensor-core GEMM + bias
    k_gemm<<<(NN + 63) / 64, 256>>>(X, b, out);
}